// round 12
// baseline (speedup 1.0000x reference)
#include <cuda_runtime.h>
#include <cuda_bf16.h>
#include <math.h>
#include <stdint.h>

// ---------------- problem sizes ----------------
#define NTOK  8192
#define DDIM  512
#define NEXP  8
#define HDIM  512
#define NPAIR (NTOK * 2)

// ---------------- device scratch (allocation-free) ----------------
__device__ int   g_cnt[NEXP];          // zero at load; re-zeroed by reset_cnt_kernel
__device__ int   g_list[NEXP * NTOK];
__device__ float g_w[NPAIR];
__device__ __nv_bfloat16 g_xh[NTOK * DDIM];
__device__ __nv_bfloat16 g_xl[NTOK * DDIM];
__device__ __nv_bfloat16 g_w1h[NEXP * DDIM * HDIM];   // transposed: [e][n][k]
__device__ __nv_bfloat16 g_w1l[NEXP * DDIM * HDIM];
__device__ __nv_bfloat16 g_w2h[NEXP * HDIM * HDIM];
__device__ __nv_bfloat16 g_w2l[NEXP * HDIM * HDIM];
__device__ __nv_bfloat16 g_hh[(size_t)NPAIR * HDIM];
__device__ __nv_bfloat16 g_hl[(size_t)NPAIR * HDIM];

// ---------------- helpers ----------------
__device__ __forceinline__ uint32_t smem_u32(const void* p) {
    uint32_t a;
    asm("{ .reg .u64 t; cvta.to.shared.u64 t, %1; cvt.u32.u64 %0, t; }" : "=r"(a) : "l"(p));
    return a;
}

#define CP16(dst, src, ok) do {                                              \
    int _sz = (ok) ? 16 : 0;                                                 \
    asm volatile("cp.async.cg.shared.global [%0], [%1], 16, %2;"             \
                 :: "r"(dst), "l"(src), "r"(_sz));                           \
} while (0)
#define CP_COMMIT() asm volatile("cp.async.commit_group;" ::: "memory")
#define CP_WAIT(n)  asm volatile("cp.async.wait_group %0;" :: "n"(n) : "memory")

#define LDSM_X4(r0, r1, r2, r3, a)                                           \
    asm volatile("ldmatrix.sync.aligned.m8n8.x4.shared.b16 {%0,%1,%2,%3}, [%4];" \
                 : "=r"(r0), "=r"(r1), "=r"(r2), "=r"(r3) : "r"(a))

#define MMA16816(c, A, B)                                                    \
    asm volatile("mma.sync.aligned.m16n8k16.row.col.f32.bf16.bf16.f32 "      \
        "{%0,%1,%2,%3}, {%4,%5,%6,%7}, {%8,%9}, {%0,%1,%2,%3};"              \
        : "+f"((c)[0]), "+f"((c)[1]), "+f"((c)[2]), "+f"((c)[3])             \
        : "r"((A)[0]), "r"((A)[1]), "r"((A)[2]), "r"((A)[3]),                \
          "r"((B)[0]), "r"((B)[1]))

// ---------------------------------------------------------------------------
// fused prep: blocks [0,512) do gate+split_x+zero-out; blocks [512,4608)
// transpose+split W1/W2. g_cnt starts zeroed (module load / trailing reset).
// ---------------------------------------------------------------------------
__global__ void __launch_bounds__(256)
prep_all_kernel(const float* __restrict__ x,
                const float* __restrict__ Wg,
                const float* __restrict__ bg,
                const float* __restrict__ W1,
                const float* __restrict__ W2,
                float* __restrict__ out) {
    __shared__ float sbuf[512 * 9];     // gate: Wg padded; prep: 32x33 tile
    const int bx   = blockIdx.x;
    const int tid  = threadIdx.x;

    if (bx < 512) {
        // ---------------- gate + split_x + zero ----------------
        const int wid  = tid >> 5;
        const int lane = tid & 31;
#pragma unroll
        for (int i = 0; i < 16; i++) {
            int idx = tid + i * 256;
            int d = idx >> 3, e = idx & 7;
            sbuf[d * 9 + e] = Wg[idx];
        }
        __syncthreads();

#pragma unroll
        for (int k = 0; k < 2; k++) {
            const int tok = bx * 16 + wid * 2 + k;
            const float* xr = x + (size_t)tok * DDIM;
            float acc[NEXP];
#pragma unroll
            for (int e = 0; e < NEXP; e++) acc[e] = 0.0f;
#pragma unroll
            for (int i = 0; i < 16; i++) {
                int d = lane + i * 32;
                float xv = xr[d];
                __nv_bfloat16 h = __float2bfloat16(xv);
                g_xh[(size_t)tok * DDIM + d] = h;
                g_xl[(size_t)tok * DDIM + d] = __float2bfloat16(xv - __bfloat162float(h));
                out[(size_t)tok * HDIM + d] = 0.0f;
                const float* wr = &sbuf[d * 9];
#pragma unroll
                for (int e = 0; e < NEXP; e++) acc[e] += xv * wr[e];
            }
#pragma unroll
            for (int e = 0; e < NEXP; e++)
#pragma unroll
                for (int o = 16; o > 0; o >>= 1)
                    acc[e] += __shfl_down_sync(0xffffffffu, acc[e], o);

            if (lane == 0) {
                float s[NEXP];
#pragma unroll
                for (int e = 0; e < NEXP; e++) s[e] = acc[e] + bg[e];
                int i0 = 0;
#pragma unroll
                for (int e = 1; e < NEXP; e++) if (s[e] > s[i0]) i0 = e;
                int i1 = -1;
#pragma unroll
                for (int e = 0; e < NEXP; e++) {
                    if (e == i0) continue;
                    if (i1 < 0 || s[e] > s[i1]) i1 = e;
                }
                float w0 = 1.0f / (1.0f + expf(s[i1] - s[i0]));
                float w1 = 1.0f - w0;
                int p0 = tok * 2, p1 = tok * 2 + 1;
                int s0 = atomicAdd(&g_cnt[i0], 1); g_list[i0 * NTOK + s0] = p0;
                int s1 = atomicAdd(&g_cnt[i1], 1); g_list[i1 * NTOK + s1] = p1;
                g_w[p0] = w0; g_w[p1] = w1;
            }
        }
    } else {
        // ---------------- transpose + split W ----------------
        float (*tile)[33] = (float (*)[33])sbuf;
        const int id = bx - 512;
        const int nx = id & 15, ky = (id >> 4) & 15, m = id >> 8;
        size_t off = (size_t)(m & 7) * 512 * 512;
        const float* W = (m < 8) ? (W1 + off) : (W2 + off);
        __nv_bfloat16* oh = (m < 8) ? (g_w1h + off) : (g_w2h + off);
        __nv_bfloat16* ol = (m < 8) ? (g_w1l + off) : (g_w2l + off);

        const int k0 = ky * 32, n0 = nx * 32;
        const int tx = tid & 31, ty0 = tid >> 5;  // (32, 8)
#pragma unroll
        for (int i = 0; i < 4; i++) {
            int ty = ty0 + i * 8;
            tile[ty][tx] = W[(size_t)(k0 + ty) * 512 + n0 + tx];
        }
        __syncthreads();
#pragma unroll
        for (int i = 0; i < 4; i++) {
            int ty = ty0 + i * 8;
            float v = tile[tx][ty];  // = W[k0+tx][n0+ty]
            __nv_bfloat16 h = __float2bfloat16(v);
            size_t o = (size_t)(n0 + ty) * 512 + (k0 + tx);
            oh[o] = h;
            ol[o] = __float2bfloat16(v - __bfloat162float(h));
        }
    }
}

// trailing: leave g_cnt zeroed for the next graph replay
__global__ void reset_cnt_kernel() {
    if (threadIdx.x < NEXP) g_cnt[threadIdx.x] = 0;
}

// ---------------------------------------------------------------------------
// grouped split-bf16 HMMA GEMM (mma.sync m16n8k16).
// CTA tile 128x64, K chunks of 32 (64B rows), 3-stage cp.async pipeline.
// Stage (24KB): Ah(8K)|Al(8K)|Bh(4K)|Bl(4K); 3 stages = 72KB -> 3 CTA/SM.
// 8 warps in 4x2 (M x N); each warp computes 32x32.
// MMA issue is term-major (dep distance 4) to break accumulator RAW chains.
// ---------------------------------------------------------------------------
#define NCH      16                 // 512 / 32
#define STG_BASE 1024
#define STG_SIZE 24576
#define OFF_AL   8192
#define OFF_BH   16384
#define OFF_BL   20480
#define SMEM_TOT (STG_BASE + 3 * STG_SIZE)

template <bool L2K>
__global__ void __launch_bounds__(256, 3)
moe_hmma_kernel(const float* __restrict__ b1, const float* __restrict__ b2,
                float* __restrict__ out) {
    const int e   = blockIdx.z;
    const int cnt = g_cnt[e];
    const int m0  = blockIdx.y * 128;
    if (m0 >= cnt) return;
    const int n0 = blockIdx.x * 64;

    extern __shared__ char smem[];
    const uint32_t sb = smem_u32(smem);
    int*   sIdx  = (int*)(smem);
    float* sbias = (float*)(smem + 512);

    const int tid  = threadIdx.x;
    const int wid  = tid >> 5;
    const int lane = tid & 31;

    if (tid < 128) sIdx[tid] = (m0 + tid < cnt) ? g_list[e * NTOK + m0 + tid] : -1;
    if (tid < 64)  sbias[tid] = (L2K ? b2 : b1)[e * HDIM + n0 + tid];
    __syncthreads();

    // ---- A fill lanes: row = tid>>1 (0..127), 2 chunks each ----
    const int lrow = tid >> 1;
    const int half = tid & 1;
    const int p    = sIdx[lrow];
    const bool okA = (p >= 0);
    const uint4* arh;
    const uint4* arl;
    {
        size_t ab = okA ? (L2K ? ((size_t)p * HDIM) : ((size_t)(p >> 1) * DDIM)) : 0;
        arh = (const uint4*)((L2K ? g_hh : g_xh) + ab);
        arl = (const uint4*)((L2K ? g_hl : g_xl) + ab);
    }
    // ---- B fill lanes: row = tid>>2 (0..63), 1 chunk ----
    const int brow = tid >> 2;
    const int cb   = tid & 3;
    const size_t bb = ((size_t)e * HDIM + n0 + brow) * 512;
    const uint4* brh = (const uint4*)((L2K ? g_w2h : g_w1h) + bb);
    const uint4* brl = (const uint4*)((L2K ? g_w2l : g_w1l) + bb);

    uint32_t swA[2];
#pragma unroll
    for (int i = 0; i < 2; i++) {
        int ca = half * 2 + i;
        swA[i] = (uint32_t)lrow * 64 + (uint32_t)((ca ^ ((lrow >> 1) & 3)) * 16);
    }
    const uint32_t swB = (uint32_t)brow * 64 + (uint32_t)((cb ^ ((brow >> 1) & 3)) * 16);

    // ---- accumulators: warp tile 32x32 ----
    float acc[2][4][4];
#pragma unroll
    for (int mt = 0; mt < 2; mt++)
#pragma unroll
        for (int nt = 0; nt < 4; nt++)
#pragma unroll
            for (int j = 0; j < 4; j++) acc[mt][nt][j] = 0.0f;

    const int wm = wid >> 1;          // 0..3
    const int wn = wid & 1;           // 0..1
    const int lq = lane >> 3;
    const int lr = lane & 7;
    const int aRow0 = wm * 32 + lr + 8 * (lq & 1);
    const int aC    = lq >> 1;
    const int bRow0 = wn * 32 + (lq >> 1) * 8 + lr;
    const int bC    = lq & 1;
    const uint32_t sAx = (uint32_t)((aRow0 >> 1) & 3);
    const uint32_t sBx = (uint32_t)((bRow0 >> 1) & 3);
    uint32_t xoA[2], xoB[2];
#pragma unroll
    for (int b = 0; b < 2; b++) {
        xoA[b] = (uint32_t)(((b * 2 + aC) ^ sAx) * 16);
        xoB[b] = (uint32_t)(((b * 2 + bC) ^ sBx) * 16);
    }
    const uint32_t aBase = (uint32_t)aRow0 * 64;
    const uint32_t bBase = (uint32_t)bRow0 * 64;

    auto fill = [&](int c, int s) {
        uint32_t base = sb + STG_BASE + (uint32_t)s * STG_SIZE;
        int kq = c * 4;
#pragma unroll
        for (int i = 0; i < 2; i++) {
            int ca = half * 2 + i;
            uint32_t d = base + swA[i];
            CP16(d,          arh + kq + ca, okA);
            CP16(d + OFF_AL, arl + kq + ca, okA);
        }
        CP16(base + OFF_BH + swB, brh + kq + cb, true);
        CP16(base + OFF_BL + swB, brl + kq + cb, true);
        CP_COMMIT();
    };

    fill(0, 0);
    fill(1, 1);

    int s = 0;
    for (int c = 0; c < NCH; c++) {
        CP_WAIT(1);
        __syncthreads();
        if (c + 2 < NCH) fill(c + 2, (s + 2 >= 3) ? s - 1 : s + 2);
        else             CP_COMMIT();

        const uint32_t stg = sb + STG_BASE + (uint32_t)s * STG_SIZE;
#pragma unroll
        for (int b = 0; b < 2; b++) {
            uint32_t bh[8], bl[8];
#pragma unroll
            for (int bp = 0; bp < 2; bp++) {
                uint32_t off = bBase + (uint32_t)bp * 1024 + xoB[b];
                LDSM_X4(bh[bp*4+0], bh[bp*4+1], bh[bp*4+2], bh[bp*4+3],
                        stg + OFF_BH + off);
                LDSM_X4(bl[bp*4+0], bl[bp*4+1], bl[bp*4+2], bl[bp*4+3],
                        stg + OFF_BL + off);
            }
#pragma unroll
            for (int mt = 0; mt < 2; mt++) {
                uint32_t ah[4], al[4];
                uint32_t off = aBase + (uint32_t)mt * 1024 + xoA[b];
                LDSM_X4(ah[0], ah[1], ah[2], ah[3], stg + off);
                LDSM_X4(al[0], al[1], al[2], al[3], stg + OFF_AL + off);
                // term-major: dependent reuse distance = 4
#pragma unroll
                for (int nt = 0; nt < 4; nt++) MMA16816(acc[mt][nt], ah, bh + nt * 2);
#pragma unroll
                for (int nt = 0; nt < 4; nt++) MMA16816(acc[mt][nt], ah, bl + nt * 2);
#pragma unroll
                for (int nt = 0; nt < 4; nt++) MMA16816(acc[mt][nt], al, bh + nt * 2);
            }
        }
        s = (s + 1 >= 3) ? 0 : s + 1;
    }

    // ---- epilogue ----
    const int eg  = lane >> 2;
    const int tig = lane & 3;
#pragma unroll
    for (int mt = 0; mt < 2; mt++) {
#pragma unroll
        for (int hrow = 0; hrow < 2; hrow++) {
            const int rl = wm * 32 + mt * 16 + eg + hrow * 8;
            const int pp = sIdx[rl];
            if (pp < 0) continue;
            const float gw = L2K ? g_w[pp] : 0.0f;
#pragma unroll
            for (int nt = 0; nt < 4; nt++) {
                const int cl = wn * 32 + nt * 8 + tig * 2;
                float v0 = acc[mt][nt][hrow * 2 + 0] + sbias[cl];
                float v1 = acc[mt][nt][hrow * 2 + 1] + sbias[cl + 1];
                if (!L2K) {
                    v0 = 0.5f * v0 * (1.0f + erff(v0 * 0.70710678118654752f));
                    v1 = 0.5f * v1 * (1.0f + erff(v1 * 0.70710678118654752f));
                    __nv_bfloat16 h0 = __float2bfloat16(v0);
                    __nv_bfloat16 h1 = __float2bfloat16(v1);
                    __nv_bfloat16 l0 = __float2bfloat16(v0 - __bfloat162float(h0));
                    __nv_bfloat16 l1 = __float2bfloat16(v1 - __bfloat162float(h1));
                    size_t o = (size_t)pp * HDIM + n0 + cl;
                    *(__nv_bfloat162*)(g_hh + o) = __nv_bfloat162(h0, h1);
                    *(__nv_bfloat162*)(g_hl + o) = __nv_bfloat162(l0, l1);
                } else {
                    size_t o = (size_t)(pp >> 1) * HDIM + n0 + cl;
                    atomicAdd(&out[o],     v0 * gw);
                    atomicAdd(&out[o + 1], v1 * gw);
                }
            }
        }
    }
}

// ---------------------------------------------------------------------------
extern "C" void kernel_launch(void* const* d_in, const int* in_sizes, int n_in,
                              void* d_out, int out_size) {
    const float* x  = (const float*)d_in[0];
    const float* Wg = (const float*)d_in[1];
    const float* bg = (const float*)d_in[2];
    const float* W1 = (const float*)d_in[3];
    const float* b1 = (const float*)d_in[4];
    const float* W2 = (const float*)d_in[5];
    const float* b2 = (const float*)d_in[6];
    float* out = (float*)d_out;

    cudaFuncSetAttribute(moe_hmma_kernel<false>,
                         cudaFuncAttributeMaxDynamicSharedMemorySize, SMEM_TOT);
    cudaFuncSetAttribute(moe_hmma_kernel<true>,
                         cudaFuncAttributeMaxDynamicSharedMemorySize, SMEM_TOT);

    prep_all_kernel<<<512 + 4096, 256>>>(x, Wg, bg, W1, W2, out);

    dim3 grid(HDIM / 64, NTOK / 128, NEXP);
    moe_hmma_kernel<false><<<grid, 256, SMEM_TOT>>>(b1, b2, out);
    moe_hmma_kernel<true ><<<grid, 256, SMEM_TOT>>>(b1, b2, out);

    reset_cnt_kernel<<<1, 32>>>();   // leave g_cnt zeroed for next replay
}

// round 14
// speedup vs baseline: 1.0367x; 1.0367x over previous
#include <cuda_runtime.h>
#include <cuda_bf16.h>
#include <math.h>
#include <stdint.h>

// ---------------- problem sizes ----------------
#define NTOK  8192
#define DDIM  512
#define NEXP  8
#define HDIM  512
#define NPAIR (NTOK * 2)

// ---------------- device scratch (allocation-free) ----------------
__device__ int   g_cnt[NEXP];
__device__ int   g_list[NEXP * NTOK];
__device__ float g_w[NPAIR];
__device__ __nv_bfloat16 g_xh[NTOK * DDIM];
__device__ __nv_bfloat16 g_xl[NTOK * DDIM];
__device__ __nv_bfloat16 g_w1h[NEXP * DDIM * HDIM];   // transposed: [e][n][k]
__device__ __nv_bfloat16 g_w1l[NEXP * DDIM * HDIM];
__device__ __nv_bfloat16 g_w2h[NEXP * HDIM * HDIM];
__device__ __nv_bfloat16 g_w2l[NEXP * HDIM * HDIM];
__device__ __nv_bfloat16 g_hh[(size_t)NPAIR * HDIM];
__device__ __nv_bfloat16 g_hl[(size_t)NPAIR * HDIM];

// ---------------- helpers ----------------
__device__ __forceinline__ uint32_t smem_u32(const void* p) {
    uint32_t a;
    asm("{ .reg .u64 t; cvta.to.shared.u64 t, %1; cvt.u32.u64 %0, t; }" : "=r"(a) : "l"(p));
    return a;
}

#define CP16(dst, src, ok) do {                                              \
    int _sz = (ok) ? 16 : 0;                                                 \
    asm volatile("cp.async.cg.shared.global [%0], [%1], 16, %2;"             \
                 :: "r"(dst), "l"(src), "r"(_sz));                           \
} while (0)
#define CP_COMMIT() asm volatile("cp.async.commit_group;" ::: "memory")
#define CP_WAIT(n)  asm volatile("cp.async.wait_group %0;" :: "n"(n) : "memory")

#define LDSM_X4(r0, r1, r2, r3, a)                                           \
    asm volatile("ldmatrix.sync.aligned.m8n8.x4.shared.b16 {%0,%1,%2,%3}, [%4];" \
                 : "=r"(r0), "=r"(r1), "=r"(r2), "=r"(r3) : "r"(a))

#define MMA16816(c, A, B)                                                    \
    asm volatile("mma.sync.aligned.m16n8k16.row.col.f32.bf16.bf16.f32 "      \
        "{%0,%1,%2,%3}, {%4,%5,%6,%7}, {%8,%9}, {%0,%1,%2,%3};"              \
        : "+f"((c)[0]), "+f"((c)[1]), "+f"((c)[2]), "+f"((c)[3])             \
        : "r"((A)[0]), "r"((A)[1]), "r"((A)[2]), "r"((A)[3]),                \
          "r"((B)[0]), "r"((B)[1]))

// ---------------------------------------------------------------------------
// prep_w: transpose W[e][k][n] -> Wt[e][n][k], split to bf16 hi/lo.
// Also zeroes g_cnt (block (0,0,0)) -- runs before the gate kernel.
// ---------------------------------------------------------------------------
__global__ void prep_w_kernel(const float* __restrict__ W1,
                              const float* __restrict__ W2) {
    __shared__ float tile[32][33];
    if (blockIdx.x == 0 && blockIdx.y == 0 && blockIdx.z == 0 &&
        threadIdx.y == 0 && threadIdx.x < NEXP)
        g_cnt[threadIdx.x] = 0;

    int m = blockIdx.z;
    size_t off = (size_t)(m & 7) * 512 * 512;
    const float* W = (m < 8) ? (W1 + off) : (W2 + off);
    __nv_bfloat16* oh = (m < 8) ? (g_w1h + off) : (g_w2h + off);
    __nv_bfloat16* ol = (m < 8) ? (g_w1l + off) : (g_w2l + off);

    int k0 = blockIdx.y * 32, n0 = blockIdx.x * 32;
    int tx = threadIdx.x, ty0 = threadIdx.y;  // (32, 8)
#pragma unroll
    for (int i = 0; i < 4; i++) {
        int ty = ty0 + i * 8;
        tile[ty][tx] = W[(size_t)(k0 + ty) * 512 + n0 + tx];
    }
    __syncthreads();
#pragma unroll
    for (int i = 0; i < 4; i++) {
        int ty = ty0 + i * 8;
        float v = tile[tx][ty];  // = W[k0+tx][n0+ty]
        __nv_bfloat16 h = __float2bfloat16(v);
        size_t o = (size_t)(n0 + ty) * 512 + (k0 + tx);
        oh[o] = h;
        ol[o] = __float2bfloat16(v - __bfloat162float(h));
    }
}

// ---------------------------------------------------------------------------
// fused gate + split_x + zero-out. 512 blocks x 256 threads.
// ---------------------------------------------------------------------------
__global__ void __launch_bounds__(256)
gate_split_kernel(const float* __restrict__ x,
                  const float* __restrict__ Wg,
                  const float* __restrict__ bg,
                  float* __restrict__ out) {
    __shared__ float sWg[512 * 9];
    const int tid  = threadIdx.x;
    const int wid  = tid >> 5;
    const int lane = tid & 31;

#pragma unroll
    for (int i = 0; i < 16; i++) {
        int idx = tid + i * 256;
        int d = idx >> 3, e = idx & 7;
        sWg[d * 9 + e] = Wg[idx];
    }
    __syncthreads();

#pragma unroll
    for (int k = 0; k < 2; k++) {
        const int tok = blockIdx.x * 16 + wid * 2 + k;
        const float* xr = x + (size_t)tok * DDIM;
        float acc[NEXP];
#pragma unroll
        for (int e = 0; e < NEXP; e++) acc[e] = 0.0f;
#pragma unroll
        for (int i = 0; i < 16; i++) {
            int d = lane + i * 32;
            float xv = xr[d];
            __nv_bfloat16 h = __float2bfloat16(xv);
            g_xh[(size_t)tok * DDIM + d] = h;
            g_xl[(size_t)tok * DDIM + d] = __float2bfloat16(xv - __bfloat162float(h));
            out[(size_t)tok * HDIM + d] = 0.0f;
            const float* wr = &sWg[d * 9];
#pragma unroll
            for (int e = 0; e < NEXP; e++) acc[e] += xv * wr[e];
        }
#pragma unroll
        for (int e = 0; e < NEXP; e++)
#pragma unroll
            for (int o = 16; o > 0; o >>= 1)
                acc[e] += __shfl_down_sync(0xffffffffu, acc[e], o);

        if (lane == 0) {
            float s[NEXP];
#pragma unroll
            for (int e = 0; e < NEXP; e++) s[e] = acc[e] + bg[e];
            int i0 = 0;
#pragma unroll
            for (int e = 1; e < NEXP; e++) if (s[e] > s[i0]) i0 = e;
            int i1 = -1;
#pragma unroll
            for (int e = 0; e < NEXP; e++) {
                if (e == i0) continue;
                if (i1 < 0 || s[e] > s[i1]) i1 = e;
            }
            float w0 = 1.0f / (1.0f + expf(s[i1] - s[i0]));
            float w1 = 1.0f - w0;
            int p0 = tok * 2, p1 = tok * 2 + 1;
            int s0 = atomicAdd(&g_cnt[i0], 1); g_list[i0 * NTOK + s0] = p0;
            int s1 = atomicAdd(&g_cnt[i1], 1); g_list[i1 * NTOK + s1] = p1;
            g_w[p0] = w0; g_w[p1] = w1;
        }
    }
}

// ---------------------------------------------------------------------------
// grouped split-bf16 HMMA GEMM (mma.sync m16n8k16).
// CTA tile 128x128, K chunks of 32 (64B rows), 3-stage cp.async pipeline.
// Stage (32KB): Ah(8K)|Al(8K)|Bh(8K)|Bl(8K); 3 stages = 96KB -> 2 CTA/SM.
// 8 warps in 2x4 (M x N); warp tile 64x32 (4 mt x 4 nt).
// Per mt, MMA issue is term-major over nt (dep distance 4).
// 64B-row swizzle: chunk' = chunk ^ ((row>>1)&3)  (conflict-free ldmatrix).
// ---------------------------------------------------------------------------
#define NCH      16                 // 512 / 32
#define STG_BASE 1024
#define STG_SIZE 32768
#define OFF_AL   8192
#define OFF_BH   16384
#define OFF_BL   24576
#define SMEM_TOT (STG_BASE + 3 * STG_SIZE)

template <bool L2K>
__global__ void __launch_bounds__(256, 2)
moe_hmma_kernel(const float* __restrict__ b1, const float* __restrict__ b2,
                float* __restrict__ out) {
    const int e   = blockIdx.z;
    const int cnt = g_cnt[e];
    const int m0  = blockIdx.y * 128;
    if (m0 >= cnt) return;
    const int n0 = blockIdx.x * 128;

    extern __shared__ char smem[];
    const uint32_t sb = smem_u32(smem);
    int*   sIdx  = (int*)(smem);
    float* sbias = (float*)(smem + 512);

    const int tid  = threadIdx.x;
    const int wid  = tid >> 5;
    const int lane = tid & 31;

    if (tid < 128) {
        sIdx[tid]  = (m0 + tid < cnt) ? g_list[e * NTOK + m0 + tid] : -1;
        sbias[tid] = (L2K ? b2 : b1)[e * HDIM + n0 + tid];
    }
    __syncthreads();

    // ---- fill lanes: row = tid>>1 (0..127), half = tid&1; 2 uint4 per buffer ----
    const int lrow = tid >> 1;
    const int half = tid & 1;
    const int p    = sIdx[lrow];
    const bool okA = (p >= 0);
    const uint4* arh;
    const uint4* arl;
    {
        size_t ab = okA ? (L2K ? ((size_t)p * HDIM) : ((size_t)(p >> 1) * DDIM)) : 0;
        arh = (const uint4*)((L2K ? g_hh : g_xh) + ab);
        arl = (const uint4*)((L2K ? g_hl : g_xl) + ab);
    }
    const size_t bb = ((size_t)e * HDIM + n0 + lrow) * 512;
    const uint4* brh = (const uint4*)((L2K ? g_w2h : g_w1h) + bb);
    const uint4* brl = (const uint4*)((L2K ? g_w2l : g_w1l) + bb);

    // swizzled dst offsets (per-thread constants); chunk has 4 uint4, thread owns 2
    uint32_t sw[2];
#pragma unroll
    for (int i = 0; i < 2; i++) {
        int ca = half * 2 + i;
        sw[i] = (uint32_t)lrow * 64 + (uint32_t)((ca ^ ((lrow >> 1) & 3)) * 16);
    }

    // ---- accumulators: warp tile 64x32 ----
    float acc[4][4][4];
#pragma unroll
    for (int mt = 0; mt < 4; mt++)
#pragma unroll
        for (int nt = 0; nt < 4; nt++)
#pragma unroll
            for (int j = 0; j < 4; j++) acc[mt][nt][j] = 0.0f;

    const int wm = wid >> 2;          // 0..1
    const int wn = wid & 3;           // 0..3
    const int lq = lane >> 3;
    const int lr = lane & 7;
    const int aRow0 = wm * 64 + lr + 8 * (lq & 1);
    const int aC    = lq >> 1;
    const int bRow0 = wn * 32 + (lq >> 1) * 8 + lr;
    const int bC    = lq & 1;
    const uint32_t sAx = (uint32_t)((aRow0 >> 1) & 3);
    const uint32_t sBx = (uint32_t)((bRow0 >> 1) & 3);
    uint32_t xoA[2], xoB[2];
#pragma unroll
    for (int b = 0; b < 2; b++) {
        xoA[b] = (uint32_t)(((b * 2 + aC) ^ sAx) * 16);
        xoB[b] = (uint32_t)(((b * 2 + bC) ^ sBx) * 16);
    }
    const uint32_t aBase = (uint32_t)aRow0 * 64;
    const uint32_t bBase = (uint32_t)bRow0 * 64;

    auto fill = [&](int c, int s) {
        uint32_t base = sb + STG_BASE + (uint32_t)s * STG_SIZE;
        int kq = c * 4;
#pragma unroll
        for (int i = 0; i < 2; i++) {
            int ca = half * 2 + i;
            uint32_t d = base + sw[i];
            CP16(d,          arh + kq + ca, okA);
            CP16(d + OFF_AL, arl + kq + ca, okA);
            CP16(d + OFF_BH, brh + kq + ca, true);
            CP16(d + OFF_BL, brl + kq + ca, true);
        }
        CP_COMMIT();
    };

    fill(0, 0);
    fill(1, 1);

    int s = 0;
    for (int c = 0; c < NCH; c++) {
        CP_WAIT(1);
        __syncthreads();
        if (c + 2 < NCH) fill(c + 2, (s + 2 >= 3) ? s - 1 : s + 2);
        else             CP_COMMIT();

        const uint32_t stg = sb + STG_BASE + (uint32_t)s * STG_SIZE;
#pragma unroll
        for (int b = 0; b < 2; b++) {
            uint32_t bh[8], bl[8];
#pragma unroll
            for (int bp = 0; bp < 2; bp++) {
                uint32_t off = bBase + (uint32_t)bp * 1024 + xoB[b];
                LDSM_X4(bh[bp*4+0], bh[bp*4+1], bh[bp*4+2], bh[bp*4+3],
                        stg + OFF_BH + off);
                LDSM_X4(bl[bp*4+0], bl[bp*4+1], bl[bp*4+2], bl[bp*4+3],
                        stg + OFF_BL + off);
            }
#pragma unroll
            for (int mt = 0; mt < 4; mt++) {
                uint32_t ah[4], al[4];
                uint32_t off = aBase + (uint32_t)mt * 1024 + xoA[b];
                LDSM_X4(ah[0], ah[1], ah[2], ah[3], stg + off);
                LDSM_X4(al[0], al[1], al[2], al[3], stg + OFF_AL + off);
                // term-major within mt: dep distance 4
#pragma unroll
                for (int nt = 0; nt < 4; nt++) MMA16816(acc[mt][nt], ah, bh + nt * 2);
#pragma unroll
                for (int nt = 0; nt < 4; nt++) MMA16816(acc[mt][nt], ah, bl + nt * 2);
#pragma unroll
                for (int nt = 0; nt < 4; nt++) MMA16816(acc[mt][nt], al, bh + nt * 2);
            }
        }
        s = (s + 1 >= 3) ? 0 : s + 1;
    }

    // ---- epilogue ----
    const int eg  = lane >> 2;
    const int tig = lane & 3;
#pragma unroll
    for (int mt = 0; mt < 4; mt++) {
#pragma unroll
        for (int hrow = 0; hrow < 2; hrow++) {
            const int rl = wm * 64 + mt * 16 + eg + hrow * 8;
            const int pp = sIdx[rl];
            if (pp < 0) continue;
            const float gw = L2K ? g_w[pp] : 0.0f;
#pragma unroll
            for (int nt = 0; nt < 4; nt++) {
                const int cl = wn * 32 + nt * 8 + tig * 2;
                float v0 = acc[mt][nt][hrow * 2 + 0] + sbias[cl];
                float v1 = acc[mt][nt][hrow * 2 + 1] + sbias[cl + 1];
                if (!L2K) {
                    v0 = 0.5f * v0 * (1.0f + erff(v0 * 0.70710678118654752f));
                    v1 = 0.5f * v1 * (1.0f + erff(v1 * 0.70710678118654752f));
                    __nv_bfloat16 h0 = __float2bfloat16(v0);
                    __nv_bfloat16 h1 = __float2bfloat16(v1);
                    __nv_bfloat16 l0 = __float2bfloat16(v0 - __bfloat162float(h0));
                    __nv_bfloat16 l1 = __float2bfloat16(v1 - __bfloat162float(h1));
                    size_t o = (size_t)pp * HDIM + n0 + cl;
                    *(__nv_bfloat162*)(g_hh + o) = __nv_bfloat162(h0, h1);
                    *(__nv_bfloat162*)(g_hl + o) = __nv_bfloat162(l0, l1);
                } else {
                    size_t o = (size_t)(pp >> 1) * HDIM + n0 + cl;
                    atomicAdd(&out[o],     v0 * gw);
                    atomicAdd(&out[o + 1], v1 * gw);
                }
            }
        }
    }
}

// ---------------------------------------------------------------------------
extern "C" void kernel_launch(void* const* d_in, const int* in_sizes, int n_in,
                              void* d_out, int out_size) {
    const float* x  = (const float*)d_in[0];
    const float* Wg = (const float*)d_in[1];
    const float* bg = (const float*)d_in[2];
    const float* W1 = (const float*)d_in[3];
    const float* b1 = (const float*)d_in[4];
    const float* W2 = (const float*)d_in[5];
    const float* b2 = (const float*)d_in[6];
    float* out = (float*)d_out;

    cudaFuncSetAttribute(moe_hmma_kernel<false>,
                         cudaFuncAttributeMaxDynamicSharedMemorySize, SMEM_TOT);
    cudaFuncSetAttribute(moe_hmma_kernel<true>,
                         cudaFuncAttributeMaxDynamicSharedMemorySize, SMEM_TOT);

    prep_w_kernel<<<dim3(16, 16, 16), dim3(32, 8)>>>(W1, W2);   // also zeroes g_cnt
    gate_split_kernel<<<NTOK / 16, 256>>>(x, Wg, bg, out);      // gate + split + zero

    dim3 grid(HDIM / 128, NTOK / 128, NEXP);
    moe_hmma_kernel<false><<<grid, 256, SMEM_TOT>>>(b1, b2, out);
    moe_hmma_kernel<true ><<<grid, 256, SMEM_TOT>>>(b1, b2, out);
}

// round 15
// speedup vs baseline: 1.2351x; 1.1913x over previous
#include <cuda_runtime.h>
#include <cuda_bf16.h>
#include <math.h>
#include <stdint.h>

// ---------------- problem sizes ----------------
#define NTOK  8192
#define DDIM  512
#define NEXP  8
#define HDIM  512
#define NPAIR (NTOK * 2)

// ---------------- device scratch (allocation-free) ----------------
__device__ int   g_cnt[NEXP];
__device__ int   g_list[NEXP * NTOK];
__device__ float g_w[NPAIR];
__device__ __nv_bfloat16 g_xh[NTOK * DDIM];
__device__ __nv_bfloat16 g_xl[NTOK * DDIM];
__device__ __nv_bfloat16 g_w1h[NEXP * DDIM * HDIM];   // transposed: [e][n][k]
__device__ __nv_bfloat16 g_w1l[NEXP * DDIM * HDIM];
__device__ __nv_bfloat16 g_w2h[NEXP * HDIM * HDIM];
__device__ __nv_bfloat16 g_w2l[NEXP * HDIM * HDIM];
__device__ __nv_bfloat16 g_hh[(size_t)NPAIR * HDIM];
__device__ __nv_bfloat16 g_hl[(size_t)NPAIR * HDIM];

// ---------------- helpers ----------------
__device__ __forceinline__ uint32_t smem_u32(const void* p) {
    uint32_t a;
    asm("{ .reg .u64 t; cvta.to.shared.u64 t, %1; cvt.u32.u64 %0, t; }" : "=r"(a) : "l"(p));
    return a;
}

#define CP16(dst, src, ok) do {                                              \
    int _sz = (ok) ? 16 : 0;                                                 \
    asm volatile("cp.async.cg.shared.global [%0], [%1], 16, %2;"             \
                 :: "r"(dst), "l"(src), "r"(_sz));                           \
} while (0)
#define CP_COMMIT() asm volatile("cp.async.commit_group;" ::: "memory")
#define CP_WAIT(n)  asm volatile("cp.async.wait_group %0;" :: "n"(n) : "memory")

#define LDSM_X4(r0, r1, r2, r3, a)                                           \
    asm volatile("ldmatrix.sync.aligned.m8n8.x4.shared.b16 {%0,%1,%2,%3}, [%4];" \
                 : "=r"(r0), "=r"(r1), "=r"(r2), "=r"(r3) : "r"(a))

#define MMA16816(c, A, B)                                                    \
    asm volatile("mma.sync.aligned.m16n8k16.row.col.f32.bf16.bf16.f32 "      \
        "{%0,%1,%2,%3}, {%4,%5,%6,%7}, {%8,%9}, {%0,%1,%2,%3};"              \
        : "+f"((c)[0]), "+f"((c)[1]), "+f"((c)[2]), "+f"((c)[3])             \
        : "r"((A)[0]), "r"((A)[1]), "r"((A)[2]), "r"((A)[3]),                \
          "r"((B)[0]), "r"((B)[1]))

// ---------------------------------------------------------------------------
// prep_w: transpose W[e][k][n] -> Wt[e][n][k], split to bf16 hi/lo.
// Also zeroes g_cnt (block (0,0,0)) -- runs before the gate kernel.
// ---------------------------------------------------------------------------
__global__ void prep_w_kernel(const float* __restrict__ W1,
                              const float* __restrict__ W2) {
    __shared__ float tile[32][33];
    if (blockIdx.x == 0 && blockIdx.y == 0 && blockIdx.z == 0 &&
        threadIdx.y == 0 && threadIdx.x < NEXP)
        g_cnt[threadIdx.x] = 0;

    int m = blockIdx.z;
    size_t off = (size_t)(m & 7) * 512 * 512;
    const float* W = (m < 8) ? (W1 + off) : (W2 + off);
    __nv_bfloat16* oh = (m < 8) ? (g_w1h + off) : (g_w2h + off);
    __nv_bfloat16* ol = (m < 8) ? (g_w1l + off) : (g_w2l + off);

    int k0 = blockIdx.y * 32, n0 = blockIdx.x * 32;
    int tx = threadIdx.x, ty0 = threadIdx.y;  // (32, 8)
#pragma unroll
    for (int i = 0; i < 4; i++) {
        int ty = ty0 + i * 8;
        tile[ty][tx] = W[(size_t)(k0 + ty) * 512 + n0 + tx];
    }
    __syncthreads();
#pragma unroll
    for (int i = 0; i < 4; i++) {
        int ty = ty0 + i * 8;
        float v = tile[tx][ty];  // = W[k0+tx][n0+ty]
        __nv_bfloat16 h = __float2bfloat16(v);
        size_t o = (size_t)(n0 + ty) * 512 + (k0 + tx);
        oh[o] = h;
        ol[o] = __float2bfloat16(v - __bfloat162float(h));
    }
}

// ---------------------------------------------------------------------------
// fused gate + split_x + zero-out. 512 blocks x 256 threads.
// ---------------------------------------------------------------------------
__global__ void __launch_bounds__(256)
gate_split_kernel(const float* __restrict__ x,
                  const float* __restrict__ Wg,
                  const float* __restrict__ bg,
                  float* __restrict__ out) {
    __shared__ float sWg[512 * 9];
    const int tid  = threadIdx.x;
    const int wid  = tid >> 5;
    const int lane = tid & 31;

#pragma unroll
    for (int i = 0; i < 16; i++) {
        int idx = tid + i * 256;
        int d = idx >> 3, e = idx & 7;
        sWg[d * 9 + e] = Wg[idx];
    }
    __syncthreads();

#pragma unroll
    for (int k = 0; k < 2; k++) {
        const int tok = blockIdx.x * 16 + wid * 2 + k;
        const float* xr = x + (size_t)tok * DDIM;
        float acc[NEXP];
#pragma unroll
        for (int e = 0; e < NEXP; e++) acc[e] = 0.0f;
#pragma unroll
        for (int i = 0; i < 16; i++) {
            int d = lane + i * 32;
            float xv = xr[d];
            __nv_bfloat16 h = __float2bfloat16(xv);
            g_xh[(size_t)tok * DDIM + d] = h;
            g_xl[(size_t)tok * DDIM + d] = __float2bfloat16(xv - __bfloat162float(h));
            out[(size_t)tok * HDIM + d] = 0.0f;
            const float* wr = &sWg[d * 9];
#pragma unroll
            for (int e = 0; e < NEXP; e++) acc[e] += xv * wr[e];
        }
#pragma unroll
        for (int e = 0; e < NEXP; e++)
#pragma unroll
            for (int o = 16; o > 0; o >>= 1)
                acc[e] += __shfl_down_sync(0xffffffffu, acc[e], o);

        if (lane == 0) {
            float s[NEXP];
#pragma unroll
            for (int e = 0; e < NEXP; e++) s[e] = acc[e] + bg[e];
            int i0 = 0;
#pragma unroll
            for (int e = 1; e < NEXP; e++) if (s[e] > s[i0]) i0 = e;
            int i1 = -1;
#pragma unroll
            for (int e = 0; e < NEXP; e++) {
                if (e == i0) continue;
                if (i1 < 0 || s[e] > s[i1]) i1 = e;
            }
            float w0 = 1.0f / (1.0f + expf(s[i1] - s[i0]));
            float w1 = 1.0f - w0;
            int p0 = tok * 2, p1 = tok * 2 + 1;
            int s0 = atomicAdd(&g_cnt[i0], 1); g_list[i0 * NTOK + s0] = p0;
            int s1 = atomicAdd(&g_cnt[i1], 1); g_list[i1 * NTOK + s1] = p1;
            g_w[p0] = w0; g_w[p1] = w1;
        }
    }
}

// ---------------------------------------------------------------------------
// grouped split-bf16 HMMA GEMM (mma.sync m16n8k16), software-pipelined frags.
// CTA tile 128x64, K chunks of 32 (64B rows), 3-stage cp.async pipeline.
// Stage (24KB): Ah(8K)|Al(8K)|Bh(4K)|Bl(4K); 2 CTA/SM (regs ~120).
// 8 warps in 4x2 (M x N); each warp computes 32x32.
// Two register frag buffers (b0/b1): LDSM for step t+1 issues before MMAs of
// step t, so MMA issue is never blocked on ldmatrix results.
// ---------------------------------------------------------------------------
#define NCH      16                 // 512 / 32
#define STG_BASE 1024
#define STG_SIZE 24576
#define OFF_AL   8192
#define OFF_BH   16384
#define OFF_BL   20480
#define SMEM_TOT (STG_BASE + 3 * STG_SIZE)

// load all frags for half-chunk B (8 LDSM_X4)
#define LD_FRAGS(STG, BI, BH, BL, AH, AL) do {                               \
    LDSM_X4((BH)[0], (BH)[1], (BH)[2], (BH)[3],                              \
            (STG) + OFF_BH + bBase + xoB[BI]);                               \
    LDSM_X4((BH)[4], (BH)[5], (BH)[6], (BH)[7],                              \
            (STG) + OFF_BH + bBase + 1024 + xoB[BI]);                        \
    LDSM_X4((BL)[0], (BL)[1], (BL)[2], (BL)[3],                              \
            (STG) + OFF_BL + bBase + xoB[BI]);                               \
    LDSM_X4((BL)[4], (BL)[5], (BL)[6], (BL)[7],                              \
            (STG) + OFF_BL + bBase + 1024 + xoB[BI]);                        \
    LDSM_X4((AH)[0], (AH)[1], (AH)[2], (AH)[3],                              \
            (STG) + aBase + xoA[BI]);                                        \
    LDSM_X4((AH)[4], (AH)[5], (AH)[6], (AH)[7],                              \
            (STG) + aBase + 1024 + xoA[BI]);                                 \
    LDSM_X4((AL)[0], (AL)[1], (AL)[2], (AL)[3],                              \
            (STG) + OFF_AL + aBase + xoA[BI]);                               \
    LDSM_X4((AL)[4], (AL)[5], (AL)[6], (AL)[7],                              \
            (STG) + OFF_AL + aBase + 1024 + xoA[BI]);                        \
} while (0)

// 24 MMAs, term-major across both mt (dep distance 8 per accumulator)
#define MMA_STEP(BH, BL, AH, AL) do {                                        \
    _Pragma("unroll")                                                        \
    for (int mt = 0; mt < 2; mt++)                                           \
        _Pragma("unroll")                                                    \
        for (int nt = 0; nt < 4; nt++)                                       \
            MMA16816(acc[mt][nt], (AH) + mt * 4, (BH) + nt * 2);             \
    _Pragma("unroll")                                                        \
    for (int mt = 0; mt < 2; mt++)                                           \
        _Pragma("unroll")                                                    \
        for (int nt = 0; nt < 4; nt++)                                       \
            MMA16816(acc[mt][nt], (AH) + mt * 4, (BL) + nt * 2);             \
    _Pragma("unroll")                                                        \
    for (int mt = 0; mt < 2; mt++)                                           \
        _Pragma("unroll")                                                    \
        for (int nt = 0; nt < 4; nt++)                                       \
            MMA16816(acc[mt][nt], (AL) + mt * 4, (BH) + nt * 2);             \
} while (0)

template <bool L2K>
__global__ void __launch_bounds__(256, 2)
moe_hmma_kernel(const float* __restrict__ b1, const float* __restrict__ b2,
                float* __restrict__ out) {
    const int e   = blockIdx.z;
    const int cnt = g_cnt[e];
    const int m0  = blockIdx.y * 128;
    if (m0 >= cnt) return;
    const int n0 = blockIdx.x * 64;

    extern __shared__ char smem[];
    const uint32_t sb = smem_u32(smem);
    int*   sIdx  = (int*)(smem);
    float* sbias = (float*)(smem + 512);

    const int tid  = threadIdx.x;
    const int wid  = tid >> 5;
    const int lane = tid & 31;

    if (tid < 128) sIdx[tid] = (m0 + tid < cnt) ? g_list[e * NTOK + m0 + tid] : -1;
    if (tid < 64)  sbias[tid] = (L2K ? b2 : b1)[e * HDIM + n0 + tid];
    __syncthreads();

    // ---- A fill lanes: row = tid>>1 (0..127), 2 chunks each ----
    const int lrow = tid >> 1;
    const int half = tid & 1;
    const int p    = sIdx[lrow];
    const bool okA = (p >= 0);
    const uint4* arh;
    const uint4* arl;
    {
        size_t ab = okA ? (L2K ? ((size_t)p * HDIM) : ((size_t)(p >> 1) * DDIM)) : 0;
        arh = (const uint4*)((L2K ? g_hh : g_xh) + ab);
        arl = (const uint4*)((L2K ? g_hl : g_xl) + ab);
    }
    // ---- B fill lanes: row = tid>>2 (0..63), 1 chunk ----
    const int brow = tid >> 2;
    const int cb   = tid & 3;
    const size_t bb = ((size_t)e * HDIM + n0 + brow) * 512;
    const uint4* brh = (const uint4*)((L2K ? g_w2h : g_w1h) + bb);
    const uint4* brl = (const uint4*)((L2K ? g_w2l : g_w1l) + bb);

    uint32_t swA[2];
#pragma unroll
    for (int i = 0; i < 2; i++) {
        int ca = half * 2 + i;
        swA[i] = (uint32_t)lrow * 64 + (uint32_t)((ca ^ ((lrow >> 1) & 3)) * 16);
    }
    const uint32_t swB = (uint32_t)brow * 64 + (uint32_t)((cb ^ ((brow >> 1) & 3)) * 16);

    // ---- accumulators: warp tile 32x32 ----
    float acc[2][4][4];
#pragma unroll
    for (int mt = 0; mt < 2; mt++)
#pragma unroll
        for (int nt = 0; nt < 4; nt++)
#pragma unroll
            for (int j = 0; j < 4; j++) acc[mt][nt][j] = 0.0f;

    const int wm = wid >> 1;          // 0..3
    const int wn = wid & 1;           // 0..1
    const int lq = lane >> 3;
    const int lr = lane & 7;
    const int aRow0 = wm * 32 + lr + 8 * (lq & 1);
    const int aC    = lq >> 1;
    const int bRow0 = wn * 32 + (lq >> 1) * 8 + lr;
    const int bC    = lq & 1;
    const uint32_t sAx = (uint32_t)((aRow0 >> 1) & 3);
    const uint32_t sBx = (uint32_t)((bRow0 >> 1) & 3);
    uint32_t xoA[2], xoB[2];
#pragma unroll
    for (int b = 0; b < 2; b++) {
        xoA[b] = (uint32_t)(((b * 2 + aC) ^ sAx) * 16);
        xoB[b] = (uint32_t)(((b * 2 + bC) ^ sBx) * 16);
    }
    const uint32_t aBase = (uint32_t)aRow0 * 64;
    const uint32_t bBase = (uint32_t)bRow0 * 64;

    auto fill = [&](int c, int s) {
        uint32_t base = sb + STG_BASE + (uint32_t)s * STG_SIZE;
        int kq = c * 4;
#pragma unroll
        for (int i = 0; i < 2; i++) {
            int ca = half * 2 + i;
            uint32_t d = base + swA[i];
            CP16(d,          arh + kq + ca, okA);
            CP16(d + OFF_AL, arl + kq + ca, okA);
        }
        CP16(base + OFF_BH + swB, brh + kq + cb, true);
        CP16(base + OFF_BL + swB, brl + kq + cb, true);
        CP_COMMIT();
    };

    // frag double buffers
    uint32_t fAh[8], fAl[8], fBh[8], fBl[8];   // b0 buffer
    uint32_t gAh[8], gAl[8], gBh[8], gBl[8];   // b1 buffer

    fill(0, 0);
    fill(1, 1);
    CP_WAIT(1);
    __syncthreads();
    {
        const uint32_t stg0 = sb + STG_BASE;
        LD_FRAGS(stg0, 0, fBh, fBl, fAh, fAl);
    }

    int s = 0;
#pragma unroll 1
    for (int c = 0; c < NCH; c++) {
        const uint32_t stgc = sb + STG_BASE + (uint32_t)s * STG_SIZE;
        // 1. prefetch gmem for chunk c+2 (overwrites stage (c-1)%3; all warps
        //    passed sync(c-1), whose pre-barrier LDSMs are ordered before these writes)
        if (c + 2 < NCH) fill(c + 2, (s + 2 >= 3) ? s - 1 : s + 2);
        else             CP_COMMIT();
        // 2. LDSM b1 frags of chunk c (independent of step 3)
        LD_FRAGS(stgc, 1, gBh, gBl, gAh, gAl);
        // 3. MMAs on b0 frags (loaded last iteration -> no stall)
        MMA_STEP(fBh, fBl, fAh, fAl);
        // 4. stage c+1 ready
        CP_WAIT(1);
        __syncthreads();
        // 5. LDSM b0 frags of chunk c+1 (independent of step 6)
        const int sn = (s + 1 >= 3) ? 0 : s + 1;
        if (c + 1 < NCH) {
            const uint32_t stgn = sb + STG_BASE + (uint32_t)sn * STG_SIZE;
            LD_FRAGS(stgn, 0, fBh, fBl, fAh, fAl);
        }
        // 6. MMAs on b1 frags
        MMA_STEP(gBh, gBl, gAh, gAl);
        s = sn;
    }

    // ---- epilogue ----
    const int eg  = lane >> 2;
    const int tig = lane & 3;
#pragma unroll
    for (int mt = 0; mt < 2; mt++) {
#pragma unroll
        for (int hrow = 0; hrow < 2; hrow++) {
            const int rl = wm * 32 + mt * 16 + eg + hrow * 8;
            const int pp = sIdx[rl];
            if (pp < 0) continue;
            const float gw = L2K ? g_w[pp] : 0.0f;
#pragma unroll
            for (int nt = 0; nt < 4; nt++) {
                const int cl = wn * 32 + nt * 8 + tig * 2;
                float v0 = acc[mt][nt][hrow * 2 + 0] + sbias[cl];
                float v1 = acc[mt][nt][hrow * 2 + 1] + sbias[cl + 1];
                if (!L2K) {
                    v0 = 0.5f * v0 * (1.0f + erff(v0 * 0.70710678118654752f));
                    v1 = 0.5f * v1 * (1.0f + erff(v1 * 0.70710678118654752f));
                    __nv_bfloat16 h0 = __float2bfloat16(v0);
                    __nv_bfloat16 h1 = __float2bfloat16(v1);
                    __nv_bfloat16 l0 = __float2bfloat16(v0 - __bfloat162float(h0));
                    __nv_bfloat16 l1 = __float2bfloat16(v1 - __bfloat162float(h1));
                    size_t o = (size_t)pp * HDIM + n0 + cl;
                    *(__nv_bfloat162*)(g_hh + o) = __nv_bfloat162(h0, h1);
                    *(__nv_bfloat162*)(g_hl + o) = __nv_bfloat162(l0, l1);
                } else {
                    size_t o = (size_t)(pp >> 1) * HDIM + n0 + cl;
                    atomicAdd(&out[o],     v0 * gw);
                    atomicAdd(&out[o + 1], v1 * gw);
                }
            }
        }
    }
}

// ---------------------------------------------------------------------------
extern "C" void kernel_launch(void* const* d_in, const int* in_sizes, int n_in,
                              void* d_out, int out_size) {
    const float* x  = (const float*)d_in[0];
    const float* Wg = (const float*)d_in[1];
    const float* bg = (const float*)d_in[2];
    const float* W1 = (const float*)d_in[3];
    const float* b1 = (const float*)d_in[4];
    const float* W2 = (const float*)d_in[5];
    const float* b2 = (const float*)d_in[6];
    float* out = (float*)d_out;

    cudaFuncSetAttribute(moe_hmma_kernel<false>,
                         cudaFuncAttributeMaxDynamicSharedMemorySize, SMEM_TOT);
    cudaFuncSetAttribute(moe_hmma_kernel<true>,
                         cudaFuncAttributeMaxDynamicSharedMemorySize, SMEM_TOT);

    prep_w_kernel<<<dim3(16, 16, 16), dim3(32, 8)>>>(W1, W2);   // also zeroes g_cnt
    gate_split_kernel<<<NTOK / 16, 256>>>(x, Wg, bg, out);      // gate + split + zero

    dim3 grid(HDIM / 64, NTOK / 128, NEXP);
    moe_hmma_kernel<false><<<grid, 256, SMEM_TOT>>>(b1, b2, out);
    moe_hmma_kernel<true ><<<grid, 256, SMEM_TOT>>>(b1, b2, out);
}